// round 2
// baseline (speedup 1.0000x reference)
#include <cuda_runtime.h>
#include <cstddef>

// Problem constants
#define BB 32
#define SS 1024
#define EE 512
#define HH 1024
#define GG 4096          // 4*H
#define DKV 512

#define NBLK 256         // persistent grid size (2 per SM on 128 SMs; <=296 capacity)
#define NTHR 64

// Scratch (device globals; no allocation allowed)
__device__ float g_xg[(size_t)BB * SS * GG];   // [B][S][4H]
__device__ float g_hs[(size_t)BB * SS * HH];   // [B][S][H]
__device__ float g_h[2][BB * HH];              // ping-pong hidden state
__device__ float g_c[BB * HH];                 // cell state
__device__ float g_part[2][(size_t)BB * GG];   // k-split partial gate sums

// barrier state
__device__ unsigned int g_arrive = 0;
__device__ unsigned int g_gen = 0;

// ---------------------------------------------------------------------------
// Generic fp32 GEMM: C[M,N] = A[M,K] * W[N,K]^T + bias1 + bias2
// ---------------------------------------------------------------------------
template<int BM, int BN, int BK, int TM, int TN>
__global__ void gemm_nt_bias(const float* __restrict__ A,
                             const float* __restrict__ W,
                             const float* __restrict__ bias1,
                             const float* __restrict__ bias2,
                             float* __restrict__ C,
                             int M, int N, int K) {
    __shared__ float As[BK][BM + 4];
    __shared__ float Ws[BK][BN + 4];

    const int tid  = threadIdx.x;              // 256 threads
    const int tx   = tid % (BN / TN);
    const int ty   = tid / (BN / TN);
    const int row0 = blockIdx.y * BM;
    const int col0 = blockIdx.x * BN;

    float acc[TM][TN];
#pragma unroll
    for (int i = 0; i < TM; i++)
#pragma unroll
        for (int j = 0; j < TN; j++) acc[i][j] = 0.f;

    for (int k0 = 0; k0 < K; k0 += BK) {
#pragma unroll
        for (int l = 0; l < (BM * BK) / (256 * 4); l++) {
            int idx = tid + l * 256;
            int m   = idx / (BK / 4);
            int kq  = idx % (BK / 4);
            float4 v = *(const float4*)&A[(size_t)(row0 + m) * K + k0 + kq * 4];
            As[kq * 4 + 0][m] = v.x;
            As[kq * 4 + 1][m] = v.y;
            As[kq * 4 + 2][m] = v.z;
            As[kq * 4 + 3][m] = v.w;
        }
        {
            int n  = tid / (BK / 4);
            int kq = tid % (BK / 4);
            float4 v = *(const float4*)&W[(size_t)(col0 + n) * K + k0 + kq * 4];
            Ws[kq * 4 + 0][n] = v.x;
            Ws[kq * 4 + 1][n] = v.y;
            Ws[kq * 4 + 2][n] = v.z;
            Ws[kq * 4 + 3][n] = v.w;
        }
        __syncthreads();

#pragma unroll
        for (int k = 0; k < BK; k++) {
            float ra[TM], rw[TN];
#pragma unroll
            for (int i = 0; i < TM; i++) ra[i] = As[k][ty * TM + i];
#pragma unroll
            for (int j = 0; j < TN; j++) rw[j] = Ws[k][tx * TN + j];
#pragma unroll
            for (int i = 0; i < TM; i++)
#pragma unroll
                for (int j = 0; j < TN; j++) acc[i][j] += ra[i] * rw[j];
        }
        __syncthreads();
    }

#pragma unroll
    for (int i = 0; i < TM; i++) {
        int m = row0 + ty * TM + i;
#pragma unroll
        for (int j = 0; j < TN; j++) {
            int n = col0 + tx * TN + j;
            float b = 0.f;
            if (bias1) b += bias1[n];
            if (bias2) b += bias2[n];
            C[(size_t)m * N + n] = acc[i][j] + b;
        }
    }
}

// ---------------------------------------------------------------------------
// Grid-wide barrier (all NBLK blocks co-resident). Sense-free generation
// counter: arrivals via L2 atomic, release via atomic bump, poll via
// volatile load (L2, no L1 staleness).
// ---------------------------------------------------------------------------
__device__ __forceinline__ void grid_barrier() {
    __syncthreads();
    if (threadIdx.x == 0) {
        unsigned int gen = *((volatile unsigned int*)&g_gen);
        __threadfence();   // make this block's writes visible before arrival
        if (atomicAdd(&g_arrive, 1u) == NBLK - 1) {
            g_arrive = 0;
            __threadfence();
            atomicAdd(&g_gen, 1u);
        } else {
            while (*((volatile unsigned int*)&g_gen) == gen) { }
        }
    }
    __syncthreads();
}

// ---------------------------------------------------------------------------
// Persistent LSTM recurrence.
// Block blk: tile = blk>>1 selects gate cols [tile*32, +32) (= W_hh rows),
//            half = blk&1 selects k-range [half*512, +512).
// 64 threads, 4x4 microtile over a 32(batch) x 32(col) tile.
// Per step: partial GEMM -> barrier -> elementwise update -> barrier.
// ---------------------------------------------------------------------------
__global__ void __launch_bounds__(NTHR, 2)
lstm_persistent(const float* __restrict__ W_hh) {
    __shared__ float As[64][36];   // [k][batch]
    __shared__ float Ws[64][36];   // [k][col]

    const int tid  = threadIdx.x;
    const int blk  = blockIdx.x;
    const int tile = blk >> 1;
    const int half = blk & 1;
    const int c0   = tile * 32;        // gate-col base (W_hh row base)
    const int kbase = half * 512;

    const int tx = tid & 7;            // col group (4 cols)
    const int ty = tid >> 3;           // row group (4 batches)

    float* part0 = g_part[0];
    float* part1 = g_part[1];
    float* mypart = g_part[half];

    // init h, c
    for (int i = blk * NTHR + tid; i < BB * HH; i += NBLK * NTHR) {
        g_h[0][i] = 0.f;
        g_c[i]    = 0.f;
    }
    grid_barrier();

    for (int t = 0; t < SS; t++) {
        const float* __restrict__ hsrc = g_h[t & 1];
        float* __restrict__       hdst = g_h[(t + 1) & 1];

        float acc[4][4];
#pragma unroll
        for (int i = 0; i < 4; i++)
#pragma unroll
            for (int j = 0; j < 4; j++) acc[i][j] = 0.f;

        for (int kc = 0; kc < 512; kc += 64) {
            const int k0 = kbase + kc;
            // load h chunk transposed: As[k][b]. thread: b = tid>>1, ks = (tid&1)*32
            {
                const int b  = tid >> 1;
                const int ks = (tid & 1) * 32;
                const float* hrow = &hsrc[b * HH + k0 + ks];
#pragma unroll
                for (int j = 0; j < 8; j++) {
                    float4 v = __ldcg((const float4*)&hrow[j * 4]);
                    As[ks + j * 4 + 0][b] = v.x;
                    As[ks + j * 4 + 1][b] = v.y;
                    As[ks + j * 4 + 2][b] = v.z;
                    As[ks + j * 4 + 3][b] = v.w;
                }
            }
            // load W_hh chunk transposed: Ws[k][c]. thread: c = tid>>1
            {
                const int c  = tid >> 1;
                const int ks = (tid & 1) * 32;
                const float* wrow = &W_hh[(size_t)(c0 + c) * HH + k0 + ks];
#pragma unroll
                for (int j = 0; j < 8; j++) {
                    float4 v = *((const float4*)&wrow[j * 4]);
                    Ws[ks + j * 4 + 0][c] = v.x;
                    Ws[ks + j * 4 + 1][c] = v.y;
                    Ws[ks + j * 4 + 2][c] = v.z;
                    Ws[ks + j * 4 + 3][c] = v.w;
                }
            }
            __syncthreads();

#pragma unroll
            for (int k = 0; k < 64; k++) {
                float4 a = *((const float4*)&As[k][ty * 4]);
                float4 w = *((const float4*)&Ws[k][tx * 4]);
                acc[0][0] += a.x * w.x; acc[0][1] += a.x * w.y;
                acc[0][2] += a.x * w.z; acc[0][3] += a.x * w.w;
                acc[1][0] += a.y * w.x; acc[1][1] += a.y * w.y;
                acc[1][2] += a.y * w.z; acc[1][3] += a.y * w.w;
                acc[2][0] += a.z * w.x; acc[2][1] += a.z * w.y;
                acc[2][2] += a.z * w.z; acc[2][3] += a.z * w.w;
                acc[3][0] += a.w * w.x; acc[3][1] += a.w * w.y;
                acc[3][2] += a.w * w.z; acc[3][3] += a.w * w.w;
            }
            __syncthreads();
        }

        // store partials
#pragma unroll
        for (int i = 0; i < 4; i++) {
            int b = ty * 4 + i;
            float4 v = make_float4(acc[i][0], acc[i][1], acc[i][2], acc[i][3]);
            *((float4*)&mypart[(size_t)b * GG + c0 + tx * 4]) = v;
        }

        grid_barrier();

        // elementwise update: 32768 (b,h) pairs over 16384 threads -> 2 each
        for (int idx = blk * NTHR + tid; idx < BB * HH; idx += NBLK * NTHR) {
            int b = idx >> 10;
            int h = idx & (HH - 1);
            size_t pb = (size_t)b * GG;
            size_t xb = ((size_t)b * SS + t) * GG;
            float gi = __ldcg(&part0[pb + 0 * HH + h]) + __ldcg(&part1[pb + 0 * HH + h]) + g_xg[xb + 0 * HH + h];
            float gf = __ldcg(&part0[pb + 1 * HH + h]) + __ldcg(&part1[pb + 1 * HH + h]) + g_xg[xb + 1 * HH + h];
            float gg = __ldcg(&part0[pb + 2 * HH + h]) + __ldcg(&part1[pb + 2 * HH + h]) + g_xg[xb + 2 * HH + h];
            float go = __ldcg(&part0[pb + 3 * HH + h]) + __ldcg(&part1[pb + 3 * HH + h]) + g_xg[xb + 3 * HH + h];
            float iv = 1.f / (1.f + __expf(-gi));
            float fv = 1.f / (1.f + __expf(-gf));
            float gv = tanhf(gg);
            float ov = 1.f / (1.f + __expf(-go));
            float cv = fv * g_c[idx] + iv * gv;
            float hv = ov * tanhf(cv);
            g_c[idx]  = cv;
            hdst[idx] = hv;
            g_hs[((size_t)b * SS + t) * HH + h] = hv;
        }

        grid_barrier();
    }
}

// ---------------------------------------------------------------------------
// Launch
// ---------------------------------------------------------------------------
extern "C" void kernel_launch(void* const* d_in, const int* in_sizes, int n_in,
                              void* d_out, int out_size) {
    const float* x     = (const float*)d_in[0];
    const float* W_ih  = (const float*)d_in[1];
    const float* W_hh  = (const float*)d_in[2];
    const float* b_ih  = (const float*)d_in[3];
    const float* b_hh  = (const float*)d_in[4];
    const float* W_key = (const float*)d_in[5];
    const float* b_key = (const float*)d_in[6];
    const float* W_val = (const float*)d_in[7];
    const float* b_val = (const float*)d_in[8];
    float* out = (float*)d_out;

    float* xg_ptr = nullptr;
    float* hs_ptr = nullptr;
    cudaGetSymbolAddress((void**)&xg_ptr, g_xg);
    cudaGetSymbolAddress((void**)&hs_ptr, g_hs);

    const int M = BB * SS;   // 32768

    // Phase A: xg = x @ W_ih^T + b_ih + b_hh   [32768 x 4096], K=512
    {
        dim3 grid(GG / 64, M / 128);
        gemm_nt_bias<128, 64, 16, 8, 4><<<grid, 256>>>(
            x, W_ih, b_ih, b_hh, xg_ptr, M, GG, EE);
    }

    // Phase B: persistent LSTM recurrence (single launch, software barriers)
    lstm_persistent<<<NBLK, NTHR>>>(W_hh);

    // Phase C: keys / values projections [32768 x 512], K=1024
    {
        dim3 grid(DKV / 64, M / 128);
        gemm_nt_bias<128, 64, 16, 8, 4><<<grid, 256>>>(
            hs_ptr, W_key, b_key, nullptr, out, M, DKV, HH);
        gemm_nt_bias<128, 64, 16, 8, 4><<<grid, 256>>>(
            hs_ptr, W_val, b_val, nullptr, out + (size_t)M * DKV, M, DKV, HH);
    }
}

// round 3
// speedup vs baseline: 1.3680x; 1.3680x over previous
#include <cuda_runtime.h>
#include <cstddef>

// Problem constants
#define BB 32
#define SS 1024
#define EE 512
#define HH 1024
#define GG 4096          // 4*H
#define DKV 512

#define NBLK 256         // persistent grid (2/SM on 128 SMs; capacity 296)
#define NTHR 128
#define NTILE 128        // 128 tiles x 32 gate-cols = 4096

// Scratch (device globals; no allocation allowed)
__device__ float g_xg[(size_t)BB * SS * GG];   // [B][S][4H]
__device__ float g_hs[(size_t)BB * SS * HH];   // [B][S][H]
__device__ float g_hT[2][HH * BB];             // ping-pong h, TRANSPOSED [k][b]
__device__ float g_part[NTILE][BB * 32];       // [tile][b*32 + c] half-1 partials
__device__ unsigned int g_flag[NTILE];
__device__ unsigned int g_arrive = 0;
__device__ unsigned int g_gen = 0;

// ---------------------------------------------------------------------------
// f32x2 helpers (packed dual-fp32 FMA; exact fp32 semantics)
// ---------------------------------------------------------------------------
#define FFMA2(acc, a2, w2) \
    asm("fma.rn.f32x2 %0, %1, %2, %0;" : "+l"(acc) : "l"(a2), "l"(w2))

__device__ __forceinline__ unsigned long long dup2(float s) {
    unsigned long long d;
    asm("mov.b64 %0, {%1, %1};" : "=l"(d) : "f"(s));
    return d;
}

// ---------------------------------------------------------------------------
// Generic fp32 GEMM: C[M,N] = A[M,K] * W[N,K]^T + bias1 + bias2  (phases A/C)
// ---------------------------------------------------------------------------
template<int BM, int BN, int BK, int TM, int TN>
__global__ void gemm_nt_bias(const float* __restrict__ A,
                             const float* __restrict__ W,
                             const float* __restrict__ bias1,
                             const float* __restrict__ bias2,
                             float* __restrict__ C,
                             int M, int N, int K) {
    __shared__ float As[BK][BM + 4];
    __shared__ float Ws[BK][BN + 4];

    const int tid  = threadIdx.x;              // 256 threads
    const int tx   = tid % (BN / TN);
    const int ty   = tid / (BN / TN);
    const int row0 = blockIdx.y * BM;
    const int col0 = blockIdx.x * BN;

    float acc[TM][TN];
#pragma unroll
    for (int i = 0; i < TM; i++)
#pragma unroll
        for (int j = 0; j < TN; j++) acc[i][j] = 0.f;

    for (int k0 = 0; k0 < K; k0 += BK) {
#pragma unroll
        for (int l = 0; l < (BM * BK) / (256 * 4); l++) {
            int idx = tid + l * 256;
            int m   = idx / (BK / 4);
            int kq  = idx % (BK / 4);
            float4 v = *(const float4*)&A[(size_t)(row0 + m) * K + k0 + kq * 4];
            As[kq * 4 + 0][m] = v.x;
            As[kq * 4 + 1][m] = v.y;
            As[kq * 4 + 2][m] = v.z;
            As[kq * 4 + 3][m] = v.w;
        }
        {
            int n  = tid / (BK / 4);
            int kq = tid % (BK / 4);
            float4 v = *(const float4*)&W[(size_t)(col0 + n) * K + k0 + kq * 4];
            Ws[kq * 4 + 0][n] = v.x;
            Ws[kq * 4 + 1][n] = v.y;
            Ws[kq * 4 + 2][n] = v.z;
            Ws[kq * 4 + 3][n] = v.w;
        }
        __syncthreads();

#pragma unroll
        for (int k = 0; k < BK; k++) {
            float ra[TM], rw[TN];
#pragma unroll
            for (int i = 0; i < TM; i++) ra[i] = As[k][ty * TM + i];
#pragma unroll
            for (int j = 0; j < TN; j++) rw[j] = Ws[k][tx * TN + j];
#pragma unroll
            for (int i = 0; i < TM; i++)
#pragma unroll
                for (int j = 0; j < TN; j++) acc[i][j] += ra[i] * rw[j];
        }
        __syncthreads();
    }

#pragma unroll
    for (int i = 0; i < TM; i++) {
        int m = row0 + ty * TM + i;
#pragma unroll
        for (int j = 0; j < TN; j++) {
            int n = col0 + tx * TN + j;
            float b = 0.f;
            if (bias1) b += bias1[n];
            if (bias2) b += bias2[n];
            C[(size_t)m * N + n] = acc[i][j] + b;
        }
    }
}

// ---------------------------------------------------------------------------
// Grid-wide barrier (all NBLK blocks co-resident).
// ---------------------------------------------------------------------------
__device__ __forceinline__ void grid_barrier() {
    __syncthreads();
    if (threadIdx.x == 0) {
        unsigned int gen = *((volatile unsigned int*)&g_gen);
        __threadfence();
        if (atomicAdd(&g_arrive, 1u) == NBLK - 1) {
            g_arrive = 0;
            __threadfence();
            atomicAdd(&g_gen, 1u);
        } else {
            while (*((volatile unsigned int*)&g_gen) == gen) { }
        }
    }
    __syncthreads();
}

// ---------------------------------------------------------------------------
// Persistent LSTM recurrence.
// Block pair (tile, half): tile owns 32 gate-cols = 4 gates x 8 h-indices
//   (col c = g*8 + hh  <->  W_hh row g*HH + tile*8 + hh),
// half owns k-range [half*512, half*512+512).
// W tile (32 x 512 fp32) is SMEM-resident for the whole sequence.
// Per step: 8x8-microtile FFMA2 GEMM (8-way k-sliced) -> smem layer-reduce ->
//   half1 publishes partial via per-tile flag; half0 adds, does elementwise
//   update (cell state in registers), writes hT + hs -> one grid barrier.
// ---------------------------------------------------------------------------
extern __shared__ float smem_dyn[];

__global__ void __launch_bounds__(NTHR, 2)
lstm_persistent(const float* __restrict__ W_hh) {
    float* Ws   = smem_dyn;              // [512][36]  (73,728 B)
    float* As   = smem_dyn + 18432;      // [128][36]  (18,432 B)  } overlay
    float* red  = smem_dyn + 18432;      // [8][1024]  (32,768 B)  } overlay
    float* red2 = smem_dyn + 18432 + 8192; // [1024]   ( 4,096 B)

    const int tid  = threadIdx.x;
    const int blk  = blockIdx.x;
    const int tile = blk >> 1;
    const int half = blk & 1;
    const int hb   = tile * 8;           // h-index base
    const int kbase = half * 512;

    const int layer = tid >> 4;          // 8 k-slices
    const int cg    = (tid >> 2) & 3;    // col group (8 cols)
    const int bg    = tid & 3;           // batch group (8 batches)

    // --- one-time W tile load (coalesced global, transposed to Ws[k][c]) ---
    for (int j = 0; j < 128; j++) {
        int lin = tid + j * 128;         // 0..16383
        int k = lin & 511, c = lin >> 9; // c: 0..31
        int g = c >> 3, hh = c & 7;
        Ws[k * 36 + c] = W_hh[(size_t)(g * HH + hb + hh) * HH + kbase + k];
    }

    // --- init hT[0], reset pair flag ---
    for (int i = blk * NTHR + tid; i < HH * BB; i += NBLK * NTHR)
        g_hT[0][i] = 0.f;
    if (tid == 0 && half == 0) g_flag[tile] = 0;

    // elementwise cells (half0): cell = tid and tid+128 over (hh, b)
    const int b1 = tid & 31,         hh1 = tid >> 5;
    const int b2 = (tid + 128) & 31, hh2 = (tid + 128) >> 5;
    float cst1 = 0.f, cst2 = 0.f;        // cell state lives in registers

    grid_barrier();

    for (int t = 0; t < SS; t++) {
        const float* __restrict__ hsrc = g_hT[t & 1] + kbase * BB;

        // prefetch xg for the elementwise tail (hidden under GEMM)
        float xp1[4], xp2[4];
        if (half == 0) {
            size_t base1 = ((size_t)b1 * SS + t) * GG + hb + hh1;
            size_t base2 = ((size_t)b2 * SS + t) * GG + hb + hh2;
#pragma unroll
            for (int g = 0; g < 4; g++) {
                xp1[g] = __ldcg(&g_xg[base1 + (size_t)g * HH]);
                xp2[g] = __ldcg(&g_xg[base2 + (size_t)g * HH]);
            }
        }

        unsigned long long acc[8][4];
#pragma unroll
        for (int i = 0; i < 8; i++)
#pragma unroll
            for (int j = 0; j < 4; j++) acc[i][j] = 0ull;

        for (int kc = 0; kc < 512; kc += 128) {
            __syncthreads();   // As region free (prev chunk / red overlay)
            // fill As[k][b] from transposed hT (coalesced float4)
#pragma unroll
            for (int j = 0; j < 8; j++) {
                int lin = tid + j * 128;            // 0..1023
                int kr = lin >> 3, b4 = (lin & 7) * 4;
                float4 v = __ldcg((const float4*)&hsrc[(kc + kr) * BB + b4]);
                *(float4*)&As[kr * 36 + b4] = v;
            }
            __syncthreads();

            const int k0 = layer * 16;
#pragma unroll
            for (int kk = 0; kk < 16; kk++) {
                const int kl = k0 + kk;
                const float4 a0 = *(const float4*)&As[kl * 36 + bg * 8];
                const float4 a1 = *(const float4*)&As[kl * 36 + bg * 8 + 4];
                const ulonglong2 w0 = *(const ulonglong2*)&Ws[(kc + kl) * 36 + cg * 8];
                const ulonglong2 w1 = *(const ulonglong2*)&Ws[(kc + kl) * 36 + cg * 8 + 4];
                unsigned long long a2;
#define ROWFMA(i, av) \
                a2 = dup2(av); \
                FFMA2(acc[i][0], a2, w0.x); FFMA2(acc[i][1], a2, w0.y); \
                FFMA2(acc[i][2], a2, w1.x); FFMA2(acc[i][3], a2, w1.y)
                ROWFMA(0, a0.x); ROWFMA(1, a0.y); ROWFMA(2, a0.z); ROWFMA(3, a0.w);
                ROWFMA(4, a1.x); ROWFMA(5, a1.y); ROWFMA(6, a1.z); ROWFMA(7, a1.w);
#undef ROWFMA
            }
        }

        // --- layer reduction through smem: red[layer][b*32 + c] ---
        __syncthreads();
#pragma unroll
        for (int ii = 0; ii < 8; ii++) {
            int b = bg * 8 + ii;
#pragma unroll
            for (int jp = 0; jp < 4; jp++) {
                int c = cg * 8 + jp * 2;
                *(unsigned long long*)&red[layer * 1024 + b * 32 + c] = acc[ii][jp];
            }
        }
        __syncthreads();

        float s0=0.f,s1=0.f,s2=0.f,s3=0.f,s4=0.f,s5=0.f,s6=0.f,s7=0.f;
#pragma unroll
        for (int L = 0; L < 8; L++) {
            float4 v0 = *(const float4*)&red[L * 1024 + tid * 8];
            float4 v1 = *(const float4*)&red[L * 1024 + tid * 8 + 4];
            s0 += v0.x; s1 += v0.y; s2 += v0.z; s3 += v0.w;
            s4 += v1.x; s5 += v1.y; s6 += v1.z; s7 += v1.w;
        }

        if (half == 1) {
            *(float4*)&g_part[tile][tid * 8]     = make_float4(s0, s1, s2, s3);
            *(float4*)&g_part[tile][tid * 8 + 4] = make_float4(s4, s5, s6, s7);
            __threadfence();
            __syncthreads();
            if (tid == 0) atomicExch(&g_flag[tile], (unsigned int)(t + 1));
        } else {
            *(float4*)&red2[tid * 8]     = make_float4(s0, s1, s2, s3);
            *(float4*)&red2[tid * 8 + 4] = make_float4(s4, s5, s6, s7);
            if (tid == 0) {
                while (*((volatile unsigned int*)&g_flag[tile]) != (unsigned int)(t + 1)) { }
                __threadfence();
            }
            __syncthreads();

            float* __restrict__ hdst = g_hT[(t + 1) & 1];
#pragma unroll
            for (int cell = 0; cell < 2; cell++) {
                const int b  = cell ? b2  : b1;
                const int hh = cell ? hh2 : hh1;
                const float* xp = cell ? xp2 : xp1;
                float gate[4];
#pragma unroll
                for (int g = 0; g < 4; g++) {
                    int c = g * 8 + hh;
                    gate[g] = red2[b * 32 + c]
                            + __ldcg(&g_part[tile][b * 32 + c]) + xp[g];
                }
                float iv = 1.f / (1.f + __expf(-gate[0]));
                float fv = 1.f / (1.f + __expf(-gate[1]));
                float gv = tanhf(gate[2]);
                float ov = 1.f / (1.f + __expf(-gate[3]));
                float cprev = cell ? cst2 : cst1;
                float cv = fv * cprev + iv * gv;
                float hv = ov * tanhf(cv);
                if (cell) cst2 = cv; else cst1 = cv;
                hdst[(hb + hh) * BB + b] = hv;
                g_hs[((size_t)b * SS + t) * HH + hb + hh] = hv;
            }
        }

        grid_barrier();
    }
}

// ---------------------------------------------------------------------------
// Launch
// ---------------------------------------------------------------------------
extern "C" void kernel_launch(void* const* d_in, const int* in_sizes, int n_in,
                              void* d_out, int out_size) {
    const float* x     = (const float*)d_in[0];
    const float* W_ih  = (const float*)d_in[1];
    const float* W_hh  = (const float*)d_in[2];
    const float* b_ih  = (const float*)d_in[3];
    const float* b_hh  = (const float*)d_in[4];
    const float* W_key = (const float*)d_in[5];
    const float* b_key = (const float*)d_in[6];
    const float* W_val = (const float*)d_in[7];
    const float* b_val = (const float*)d_in[8];
    float* out = (float*)d_out;

    float* xg_ptr = nullptr;
    float* hs_ptr = nullptr;
    cudaGetSymbolAddress((void**)&xg_ptr, g_xg);
    cudaGetSymbolAddress((void**)&hs_ptr, g_hs);

    const int M = BB * SS;   // 32768
    const int SMEM_BYTES = (18432 + 8192 + 1024) * 4;   // 110,592 B

    cudaFuncSetAttribute(lstm_persistent,
                         cudaFuncAttributeMaxDynamicSharedMemorySize, SMEM_BYTES);

    // Phase A: xg = x @ W_ih^T + b_ih + b_hh   [32768 x 4096], K=512
    {
        dim3 grid(GG / 64, M / 128);
        gemm_nt_bias<128, 64, 16, 8, 4><<<grid, 256>>>(
            x, W_ih, b_ih, b_hh, xg_ptr, M, GG, EE);
    }

    // Phase B: persistent LSTM recurrence (single launch)
    lstm_persistent<<<NBLK, NTHR, SMEM_BYTES>>>(W_hh);

    // Phase C: keys / values projections [32768 x 512], K=1024
    {
        dim3 grid(DKV / 64, M / 128);
        gemm_nt_bias<128, 64, 16, 8, 4><<<grid, 256>>>(
            hs_ptr, W_key, b_key, nullptr, out, M, DKV, HH);
        gemm_nt_bias<128, 64, 16, 8, 4><<<grid, 256>>>(
            hs_ptr, W_val, b_val, nullptr, out + (size_t)M * DKV, M, DKV, HH);
    }
}

// round 5
// speedup vs baseline: 1.9575x; 1.4309x over previous
#include <cuda_runtime.h>
#include <cstddef>
#include <cstdint>

// Problem constants
#define BB 32
#define SS 1024
#define EE 512
#define HH 1024
#define GG 4096          // 4*H
#define DKV 512

#define NBLK 128         // persistent grid: 1 block/SM
#define NTHR 256

#define RSTRIDE 34       // k-reduce row stride (EVEN -> float2 stays 8B-aligned)

// Scratch (device globals; no allocation allowed)
__device__ __align__(16) float g_xg[(size_t)BB * SS * GG];   // [B][S][4H]
__device__ __align__(16) float g_hs[(size_t)BB * SS * HH];   // [B][S][H] fp32
__device__ __align__(16) float g_hT[2][HH * BB];             // ping-pong h^T [k][b], tf32-rounded
__device__ unsigned int g_arrive = 0;
__device__ unsigned int g_gen = 0;

// ---------------------------------------------------------------------------
// tf32 helpers
// ---------------------------------------------------------------------------
__device__ __forceinline__ uint32_t f2tf32(float f) {
    uint32_t u;
    asm("cvt.rna.tf32.f32 %0, %1;" : "=r"(u) : "f"(f));
    return u;
}

__device__ __forceinline__ void mma_tf32(float& d0, float& d1, float& d2, float& d3,
                                         uint32_t a0, uint32_t a1, uint32_t a2, uint32_t a3,
                                         uint32_t b0, uint32_t b1) {
    asm("mma.sync.aligned.m16n8k8.row.col.f32.tf32.tf32.f32 "
        "{%0,%1,%2,%3}, {%4,%5,%6,%7}, {%8,%9}, {%0,%1,%2,%3};"
        : "+f"(d0), "+f"(d1), "+f"(d2), "+f"(d3)
        : "r"(a0), "r"(a1), "r"(a2), "r"(a3), "r"(b0), "r"(b1));
}

// ---------------------------------------------------------------------------
// Generic fp32 GEMM: C[M,N] = A[M,K] * W[N,K]^T + bias1 + bias2  (phases A/C)
// ---------------------------------------------------------------------------
template<int BM, int BN, int BK, int TM, int TN>
__global__ void gemm_nt_bias(const float* __restrict__ A,
                             const float* __restrict__ W,
                             const float* __restrict__ bias1,
                             const float* __restrict__ bias2,
                             float* __restrict__ C,
                             int M, int N, int K) {
    __shared__ float As[BK][BM + 4];
    __shared__ float Ws[BK][BN + 4];

    const int tid  = threadIdx.x;
    const int tx   = tid % (BN / TN);
    const int ty   = tid / (BN / TN);
    const int row0 = blockIdx.y * BM;
    const int col0 = blockIdx.x * BN;

    float acc[TM][TN];
#pragma unroll
    for (int i = 0; i < TM; i++)
#pragma unroll
        for (int j = 0; j < TN; j++) acc[i][j] = 0.f;

    for (int k0 = 0; k0 < K; k0 += BK) {
#pragma unroll
        for (int l = 0; l < (BM * BK) / (256 * 4); l++) {
            int idx = tid + l * 256;
            int m   = idx / (BK / 4);
            int kq  = idx % (BK / 4);
            float4 v = *(const float4*)&A[(size_t)(row0 + m) * K + k0 + kq * 4];
            As[kq * 4 + 0][m] = v.x;
            As[kq * 4 + 1][m] = v.y;
            As[kq * 4 + 2][m] = v.z;
            As[kq * 4 + 3][m] = v.w;
        }
        {
            int n  = tid / (BK / 4);
            int kq = tid % (BK / 4);
            float4 v = *(const float4*)&W[(size_t)(col0 + n) * K + k0 + kq * 4];
            Ws[kq * 4 + 0][n] = v.x;
            Ws[kq * 4 + 1][n] = v.y;
            Ws[kq * 4 + 2][n] = v.z;
            Ws[kq * 4 + 3][n] = v.w;
        }
        __syncthreads();

#pragma unroll
        for (int k = 0; k < BK; k++) {
            float ra[TM], rw[TN];
#pragma unroll
            for (int i = 0; i < TM; i++) ra[i] = As[k][ty * TM + i];
#pragma unroll
            for (int j = 0; j < TN; j++) rw[j] = Ws[k][tx * TN + j];
#pragma unroll
            for (int i = 0; i < TM; i++)
#pragma unroll
                for (int j = 0; j < TN; j++) acc[i][j] += ra[i] * rw[j];
        }
        __syncthreads();
    }

#pragma unroll
    for (int i = 0; i < TM; i++) {
        int m = row0 + ty * TM + i;
#pragma unroll
        for (int j = 0; j < TN; j++) {
            int n = col0 + tx * TN + j;
            float b = 0.f;
            if (bias1) b += bias1[n];
            if (bias2) b += bias2[n];
            C[(size_t)m * N + n] = acc[i][j] + b;
        }
    }
}

// ---------------------------------------------------------------------------
// Grid-wide barrier (all NBLK blocks co-resident).
// ---------------------------------------------------------------------------
__device__ __forceinline__ void grid_barrier() {
    __syncthreads();
    if (threadIdx.x == 0) {
        unsigned int gen = *((volatile unsigned int*)&g_gen);
        __threadfence();
        if (atomicAdd(&g_arrive, 1u) == NBLK - 1) {
            g_arrive = 0;
            __threadfence();
            atomicAdd(&g_gen, 1u);
        } else {
            while (*((volatile unsigned int*)&g_gen) == gen) { }
        }
    }
    __syncthreads();
}

// ---------------------------------------------------------------------------
// Persistent tf32-MMA LSTM recurrence.
// Block = 32 gate-rows (4 gates x 8 h-indices, hb = blk*8) over full K=1024.
// gates^T[32c x 32b] = Wtile[32 x 1024] @ hT[1024 x 32] via mma.m16n8k8.tf32.
// W fragments SMEM-resident (128 KB, loaded once). 8 warps k-split; SMEM
// k-reduce (stride RSTRIDE=34, 8B-aligned float2); cell state in registers.
// ---------------------------------------------------------------------------
extern __shared__ float smem_dyn[];

__global__ void __launch_bounds__(NTHR, 1)
lstm_persistent(const float* __restrict__ W_hh) {
    uint32_t* Wf = (uint32_t*)smem_dyn;                 // 32768 u32
    float* Bsm[2] = { smem_dyn + 32768, smem_dyn + 32768 + 9216 };
    float* red = Bsm[0];                                // overlay (<=8704 of 9216 floats)

    const int tid  = threadIdx.x;
    const int lane = tid & 31;
    const int wid  = tid >> 5;
    const int blk  = blockIdx.x;
    const int hb   = blk * 8;

    // --- one-time W fragment fill (tf32-converted) ---
    for (int idx = tid; idx < 32768; idx += NTHR) {
        int r  = idx & 3;
        int L  = (idx >> 2) & 31;
        int ks = (idx >> 7) & 127;
        int mt = idx >> 14;
        int c  = mt * 16 + (L >> 2) + (r & 1) * 8;   // gate-col 0..31
        int k  = ks * 8 + (L & 3) + (r >> 1) * 4;
        int g  = c >> 3, hh = c & 7;
        Wf[idx] = f2tf32(W_hh[(size_t)(g * HH + hb + hh) * HH + k]);
    }

    // --- init hT[0] ---
    for (int i = blk * NTHR + tid; i < HH * BB; i += NBLK * NTHR)
        g_hT[0][i] = 0.f;

    // elementwise identity: one cell per thread
    const int hh_e = tid >> 5;      // 0..7
    const int b_e  = tid & 31;      // 0..31
    float cstate = 0.f;

    // B-fill identity: thread owns subtile (ksl, ng, hf)
    const int ksl_t = tid >> 3;          // kstep within chunk 0..31
    const int ng_t  = (tid >> 1) & 3;
    const int hf_t  = tid & 1;

    grid_barrier();

    for (int t = 0; t < SS; t++) {
        const float* __restrict__ hsrc = g_hT[t & 1];

        // prefetch xg (scattered; latency hidden under GEMM)
        float xp[4];
        {
            size_t base = ((size_t)b_e * SS + t) * GG + hb + hh_e;
#pragma unroll
            for (int g = 0; g < 4; g++)
                xp[g] = __ldcg(&g_xg[base + (size_t)g * HH]);
        }

        float acc[2][4][4];
#pragma unroll
        for (int m = 0; m < 2; m++)
#pragma unroll
            for (int n = 0; n < 4; n++)
#pragma unroll
                for (int r = 0; r < 4; r++) acc[m][n][r] = 0.f;

        // load chunk 0 of hT into registers (8k x 4b subtile per thread)
        float4 rbuf[8];
        {
            const float* p = &hsrc[(ksl_t * 8) * BB + ng_t * 8 + hf_t * 4];
#pragma unroll
            for (int j = 0; j < 8; j++)
                rbuf[j] = __ldcg((const float4*)&p[j * BB]);
        }

        for (int ch = 0; ch < 4; ch++) {
            float* Bw = Bsm[ch & 1];
            // STS register subtile -> B fragment layout (base tid*36, 16B aligned)
            {
                float* dst = Bw + tid * 36;
#pragma unroll
                for (int q = 0; q < 8; q++) {
                    float4 v;
                    if (q & 1) {
                        v.x = ((const float*)&rbuf[2])[q >> 1];
                        v.y = ((const float*)&rbuf[6])[q >> 1];
                        v.z = ((const float*)&rbuf[3])[q >> 1];
                        v.w = ((const float*)&rbuf[7])[q >> 1];
                    } else {
                        v.x = ((const float*)&rbuf[0])[q >> 1];
                        v.y = ((const float*)&rbuf[4])[q >> 1];
                        v.z = ((const float*)&rbuf[1])[q >> 1];
                        v.w = ((const float*)&rbuf[5])[q >> 1];
                    }
                    *(float4*)&dst[q * 4] = v;
                }
            }
            __syncthreads();

            // prefetch next chunk (latency overlaps mma below)
            if (ch < 3) {
                const float* p = &hsrc[((ch + 1) * 256 + ksl_t * 8) * BB + ng_t * 8 + hf_t * 4];
#pragma unroll
                for (int j = 0; j < 8; j++)
                    rbuf[j] = __ldcg((const float4*)&p[j * BB]);
            }

            // mma over this chunk: warp's 4 ksteps
#pragma unroll
            for (int ksl = 0; ksl < 4; ksl++) {
                const int ksc = wid * 4 + ksl;          // kstep in chunk
                const int ksg = ch * 32 + ksc;          // global kstep
                uint4 A0 = *(const uint4*)&Wf[(0 * 128 + ksg) * 128 + lane * 4];
                uint4 A1 = *(const uint4*)&Wf[(1 * 128 + ksg) * 128 + lane * 4];
#pragma unroll
                for (int ng = 0; ng < 4; ng++) {
                    const int tsrc = ksc * 8 + ng * 2 + (lane >> 4);
                    uint2 Bv = *(const uint2*)((const uint32_t*)Bw + tsrc * 36 + (lane & 15) * 2);
                    mma_tf32(acc[0][ng][0], acc[0][ng][1], acc[0][ng][2], acc[0][ng][3],
                             A0.x, A0.y, A0.z, A0.w, Bv.x, Bv.y);
                    mma_tf32(acc[1][ng][0], acc[1][ng][1], acc[1][ng][2], acc[1][ng][3],
                             A1.x, A1.y, A1.z, A1.w, Bv.x, Bv.y);
                }
            }
            __syncthreads();
        }

        // --- k-reduction staging: acc -> red[wid][c][b], stride RSTRIDE (even) ---
#pragma unroll
        for (int mt = 0; mt < 2; mt++) {
#pragma unroll
            for (int ng = 0; ng < 4; ng++) {
                int c0 = mt * 16 + (lane >> 2);
                int b0 = ng * 8 + 2 * (lane & 3);
                *(float2*)&red[(wid * 32 + c0) * RSTRIDE + b0] =
                    make_float2(acc[mt][ng][0], acc[mt][ng][1]);
                *(float2*)&red[(wid * 32 + c0 + 8) * RSTRIDE + b0] =
                    make_float2(acc[mt][ng][2], acc[mt][ng][3]);
            }
        }
        __syncthreads();

        // --- elementwise update (one cell per thread; cell state in regs) ---
        {
            float gate[4];
#pragma unroll
            for (int g = 0; g < 4; g++) {
                float s = xp[g];
#pragma unroll
                for (int w = 0; w < 8; w++)
                    s += red[(w * 32 + g * 8 + hh_e) * RSTRIDE + b_e];
                gate[g] = s;
            }
            float iv = 1.f / (1.f + __expf(-gate[0]));
            float fv = 1.f / (1.f + __expf(-gate[1]));
            float gv = tanhf(gate[2]);
            float ov = 1.f / (1.f + __expf(-gate[3]));
            cstate = fv * cstate + iv * gv;
            float hv = ov * tanhf(cstate);
            g_hT[(t + 1) & 1][(hb + hh_e) * BB + b_e] = __uint_as_float(f2tf32(hv));
            g_hs[((size_t)b_e * SS + t) * HH + hb + hh_e] = hv;
        }

        grid_barrier();
    }
}

// ---------------------------------------------------------------------------
// Launch
// ---------------------------------------------------------------------------
extern "C" void kernel_launch(void* const* d_in, const int* in_sizes, int n_in,
                              void* d_out, int out_size) {
    const float* x     = (const float*)d_in[0];
    const float* W_ih  = (const float*)d_in[1];
    const float* W_hh  = (const float*)d_in[2];
    const float* b_ih  = (const float*)d_in[3];
    const float* b_hh  = (const float*)d_in[4];
    const float* W_key = (const float*)d_in[5];
    const float* b_key = (const float*)d_in[6];
    const float* W_val = (const float*)d_in[7];
    const float* b_val = (const float*)d_in[8];
    float* out = (float*)d_out;

    float* xg_ptr = nullptr;
    float* hs_ptr = nullptr;
    cudaGetSymbolAddress((void**)&xg_ptr, g_xg);
    cudaGetSymbolAddress((void**)&hs_ptr, g_hs);

    const int M = BB * SS;   // 32768
    const int SMEM_BYTES = (32768 + 2 * 9216) * 4;   // 204,800 B

    cudaFuncSetAttribute(lstm_persistent,
                         cudaFuncAttributeMaxDynamicSharedMemorySize, SMEM_BYTES);

    // Phase A: xg = x @ W_ih^T + b_ih + b_hh   [32768 x 4096], K=512
    {
        dim3 grid(GG / 64, M / 128);
        gemm_nt_bias<128, 64, 16, 8, 4><<<grid, 256>>>(
            x, W_ih, b_ih, b_hh, xg_ptr, M, GG, EE);
    }

    // Phase B: persistent tf32-MMA LSTM recurrence (single launch)
    lstm_persistent<<<NBLK, NTHR, SMEM_BYTES>>>(W_hh);

    // Phase C: keys / values projections [32768 x 512], K=1024
    {
        dim3 grid(DKV / 64, M / 128);
        gemm_nt_bias<128, 64, 16, 8, 4><<<grid, 256>>>(
            hs_ptr, W_key, b_key, nullptr, out, M, DKV, HH);
        gemm_nt_bias<128, 64, 16, 8, 4><<<grid, 256>>>(
            hs_ptr, W_val, b_val, nullptr, out + (size_t)M * DKV, M, DKV, HH);
    }
}

// round 6
// speedup vs baseline: 2.3697x; 1.2106x over previous
#include <cuda_runtime.h>
#include <cstddef>
#include <cstdint>

// Problem constants
#define BB 32
#define SS 1024
#define EE 512
#define HH 1024
#define GG 4096          // 4*H
#define DKV 512

#define NBLK 128         // persistent grid: 1 block/SM
#define NTHR 256

#define RSTRIDE 34       // k-reduce row stride (EVEN -> float2 stays 8B-aligned)

// Scratch (device globals; no allocation allowed)
__device__ __align__(16) float g_xg[(size_t)BB * SS * GG];   // [B][S][4H]
__device__ __align__(16) float g_hs[(size_t)BB * SS * HH];   // [B][S][H] fp32
__device__ __align__(16) float g_hT[2][HH * BB];             // ping-pong h^T [k][b], tf32-rounded
__device__ unsigned int g_arrive = 0;
__device__ unsigned int g_gen = 0;

// ---------------------------------------------------------------------------
// tf32 helpers
// ---------------------------------------------------------------------------
__device__ __forceinline__ uint32_t f2tf32(float f) {
    uint32_t u;
    asm("cvt.rna.tf32.f32 %0, %1;" : "=r"(u) : "f"(f));
    return u;
}

__device__ __forceinline__ void mma_tf32(float& d0, float& d1, float& d2, float& d3,
                                         uint32_t a0, uint32_t a1, uint32_t a2, uint32_t a3,
                                         uint32_t b0, uint32_t b1) {
    asm("mma.sync.aligned.m16n8k8.row.col.f32.tf32.tf32.f32 "
        "{%0,%1,%2,%3}, {%4,%5,%6,%7}, {%8,%9}, {%0,%1,%2,%3};"
        : "+f"(d0), "+f"(d1), "+f"(d2), "+f"(d3)
        : "r"(a0), "r"(a1), "r"(a2), "r"(a3), "r"(b0), "r"(b1));
}

// ---------------------------------------------------------------------------
// tf32 tensor-core GEMM: C[M,N] = A[M,K] * W[N,K]^T + bias1 + bias2
// BM=128, BN=128, BK=32. 256 threads = 8 warps (4m x 2n), warp tile 32x64.
// Double-buffered SMEM in mma-fragment-native layout (validated lane maps).
// ---------------------------------------------------------------------------
__global__ void __launch_bounds__(256, 2)
gemm_tf32(const float* __restrict__ A,
          const float* __restrict__ W,
          const float* __restrict__ bias1,
          const float* __restrict__ bias2,
          float* __restrict__ C,
          int M, int N, int K) {
    extern __shared__ uint32_t gsm[];   // 2 stages x (Af 4096 + Bf 4096) u32

    const int tid  = threadIdx.x;
    const int lane = tid & 31;
    const int wid  = tid >> 5;
    const int mw   = wid >> 1;          // 0..3 -> m-offset mw*32
    const int nw   = wid & 1;           // 0..1 -> n-offset nw*64
    const int row0 = blockIdx.y * 128;
    const int col0 = blockIdx.x * 128;

    float4 ra[4], rb[4];

#define LDG_TILE(k0)                                                          \
    do {                                                                      \
        _Pragma("unroll")                                                     \
        for (int i = 0; i < 4; i++) {                                         \
            int v = tid + i * 256, row = v >> 3, kq = v & 7;                  \
            ra[i] = *(const float4*)&A[(size_t)(row0 + row) * K + (k0) + kq * 4]; \
        }                                                                     \
        _Pragma("unroll")                                                     \
        for (int i = 0; i < 4; i++) {                                         \
            int v = tid + i * 256, n = v >> 3, kq = v & 7;                    \
            rb[i] = *(const float4*)&W[(size_t)(col0 + n) * K + (k0) + kq * 4]; \
        }                                                                     \
    } while (0)

#define STS_TILE(stp)                                                         \
    do {                                                                      \
        uint32_t* Af = (stp);                                                 \
        uint32_t* Bf = (stp) + 4096;                                          \
        _Pragma("unroll")                                                     \
        for (int i = 0; i < 4; i++) {                                         \
            int v = tid + i * 256, row = v >> 3, kq = v & 7;                  \
            int mt = row >> 4, rw = row & 15;                                 \
            const float* pf = (const float*)&ra[i];                           \
            _Pragma("unroll")                                                 \
            for (int e = 0; e < 4; e++) {                                     \
                int kl = kq * 4 + e, ks = kl >> 3, kk = kl & 7;               \
                int ln = (rw & 7) * 4 + (kk & 3);                             \
                int r  = (rw >> 3) + 2 * (kk >> 2);                           \
                Af[((ks * 8 + mt) * 32 + ln) * 4 + r] = f2tf32(pf[e]);        \
            }                                                                 \
        }                                                                     \
        _Pragma("unroll")                                                     \
        for (int i = 0; i < 4; i++) {                                         \
            int v = tid + i * 256, n = v >> 3, kq = v & 7;                    \
            int nt = n >> 3, nn = n & 7;                                      \
            const float* pf = (const float*)&rb[i];                           \
            _Pragma("unroll")                                                 \
            for (int e = 0; e < 4; e++) {                                     \
                int kl = kq * 4 + e, ks = kl >> 3, kk = kl & 7;               \
                int ln = nn * 4 + (kk & 3);                                   \
                int r  = kk >> 2;                                             \
                Bf[((ks * 16 + nt) * 32 + ln) * 2 + r] = f2tf32(pf[e]);       \
            }                                                                 \
        }                                                                     \
    } while (0)

    float acc[2][8][4];
#pragma unroll
    for (int i = 0; i < 2; i++)
#pragma unroll
        for (int j = 0; j < 8; j++)
#pragma unroll
            for (int r = 0; r < 4; r++) acc[i][j][r] = 0.f;

    const int niter = K / 32;
    LDG_TILE(0);
    STS_TILE(gsm);

    for (int kt = 0; kt < niter; kt++) {
        __syncthreads();
        uint32_t* st = gsm + (kt & 1) * 8192;
        if (kt + 1 < niter) LDG_TILE((kt + 1) * 32);

        uint32_t* Af = st;
        uint32_t* Bf = st + 4096;
#pragma unroll
        for (int ks = 0; ks < 4; ks++) {
            uint4 av[2];
            uint2 bv[8];
#pragma unroll
            for (int i = 0; i < 2; i++)
                av[i] = *(const uint4*)&Af[((ks * 8 + mw * 2 + i) * 32 + lane) * 4];
#pragma unroll
            for (int j = 0; j < 8; j++)
                bv[j] = *(const uint2*)&Bf[((ks * 16 + nw * 8 + j) * 32 + lane) * 2];
#pragma unroll
            for (int i = 0; i < 2; i++)
#pragma unroll
                for (int j = 0; j < 8; j++)
                    mma_tf32(acc[i][j][0], acc[i][j][1], acc[i][j][2], acc[i][j][3],
                             av[i].x, av[i].y, av[i].z, av[i].w, bv[j].x, bv[j].y);
        }
        if (kt + 1 < niter) STS_TILE(gsm + ((kt + 1) & 1) * 8192);
    }

    // epilogue
#pragma unroll
    for (int i = 0; i < 2; i++) {
#pragma unroll
        for (int j = 0; j < 8; j++) {
            int row = row0 + mw * 32 + i * 16 + (lane >> 2);
            int col = col0 + nw * 64 + j * 8 + (lane & 3) * 2;
            float bb0 = 0.f, bb1 = 0.f;
            if (bias1) { bb0 += bias1[col]; bb1 += bias1[col + 1]; }
            if (bias2) { bb0 += bias2[col]; bb1 += bias2[col + 1]; }
            *(float2*)&C[(size_t)row * N + col] =
                make_float2(acc[i][j][0] + bb0, acc[i][j][1] + bb1);
            *(float2*)&C[(size_t)(row + 8) * N + col] =
                make_float2(acc[i][j][2] + bb0, acc[i][j][3] + bb1);
        }
    }
#undef LDG_TILE
#undef STS_TILE
}

// ---------------------------------------------------------------------------
// Grid-wide barrier (all NBLK blocks co-resident).
// ---------------------------------------------------------------------------
__device__ __forceinline__ void grid_barrier() {
    __syncthreads();
    if (threadIdx.x == 0) {
        unsigned int gen = *((volatile unsigned int*)&g_gen);
        __threadfence();
        if (atomicAdd(&g_arrive, 1u) == NBLK - 1) {
            g_arrive = 0;
            __threadfence();
            atomicAdd(&g_gen, 1u);
        } else {
            while (*((volatile unsigned int*)&g_gen) == gen) { }
        }
    }
    __syncthreads();
}

// ---------------------------------------------------------------------------
// Persistent tf32-MMA LSTM recurrence (unchanged from round 5 / passing).
// ---------------------------------------------------------------------------
extern __shared__ float smem_dyn[];

__global__ void __launch_bounds__(NTHR, 1)
lstm_persistent(const float* __restrict__ W_hh) {
    uint32_t* Wf = (uint32_t*)smem_dyn;                 // 32768 u32
    float* Bsm[2] = { smem_dyn + 32768, smem_dyn + 32768 + 9216 };
    float* red = Bsm[0];                                // overlay

    const int tid  = threadIdx.x;
    const int lane = tid & 31;
    const int wid  = tid >> 5;
    const int blk  = blockIdx.x;
    const int hb   = blk * 8;

    // --- one-time W fragment fill (tf32-converted) ---
    for (int idx = tid; idx < 32768; idx += NTHR) {
        int r  = idx & 3;
        int L  = (idx >> 2) & 31;
        int ks = (idx >> 7) & 127;
        int mt = idx >> 14;
        int c  = mt * 16 + (L >> 2) + (r & 1) * 8;   // gate-col 0..31
        int k  = ks * 8 + (L & 3) + (r >> 1) * 4;
        int g  = c >> 3, hh = c & 7;
        Wf[idx] = f2tf32(W_hh[(size_t)(g * HH + hb + hh) * HH + k]);
    }

    // --- init hT[0] ---
    for (int i = blk * NTHR + tid; i < HH * BB; i += NBLK * NTHR)
        g_hT[0][i] = 0.f;

    const int hh_e = tid >> 5;      // 0..7
    const int b_e  = tid & 31;      // 0..31
    float cstate = 0.f;

    const int ksl_t = tid >> 3;          // kstep within chunk 0..31
    const int ng_t  = (tid >> 1) & 3;
    const int hf_t  = tid & 1;

    grid_barrier();

    for (int t = 0; t < SS; t++) {
        const float* __restrict__ hsrc = g_hT[t & 1];

        float xp[4];
        {
            size_t base = ((size_t)b_e * SS + t) * GG + hb + hh_e;
#pragma unroll
            for (int g = 0; g < 4; g++)
                xp[g] = __ldcg(&g_xg[base + (size_t)g * HH]);
        }

        float acc[2][4][4];
#pragma unroll
        for (int m = 0; m < 2; m++)
#pragma unroll
            for (int n = 0; n < 4; n++)
#pragma unroll
                for (int r = 0; r < 4; r++) acc[m][n][r] = 0.f;

        float4 rbuf[8];
        {
            const float* p = &hsrc[(ksl_t * 8) * BB + ng_t * 8 + hf_t * 4];
#pragma unroll
            for (int j = 0; j < 8; j++)
                rbuf[j] = __ldcg((const float4*)&p[j * BB]);
        }

        for (int ch = 0; ch < 4; ch++) {
            float* Bw = Bsm[ch & 1];
            {
                float* dst = Bw + tid * 36;
#pragma unroll
                for (int q = 0; q < 8; q++) {
                    float4 v;
                    if (q & 1) {
                        v.x = ((const float*)&rbuf[2])[q >> 1];
                        v.y = ((const float*)&rbuf[6])[q >> 1];
                        v.z = ((const float*)&rbuf[3])[q >> 1];
                        v.w = ((const float*)&rbuf[7])[q >> 1];
                    } else {
                        v.x = ((const float*)&rbuf[0])[q >> 1];
                        v.y = ((const float*)&rbuf[4])[q >> 1];
                        v.z = ((const float*)&rbuf[1])[q >> 1];
                        v.w = ((const float*)&rbuf[5])[q >> 1];
                    }
                    *(float4*)&dst[q * 4] = v;
                }
            }
            __syncthreads();

            if (ch < 3) {
                const float* p = &hsrc[((ch + 1) * 256 + ksl_t * 8) * BB + ng_t * 8 + hf_t * 4];
#pragma unroll
                for (int j = 0; j < 8; j++)
                    rbuf[j] = __ldcg((const float4*)&p[j * BB]);
            }

#pragma unroll
            for (int ksl = 0; ksl < 4; ksl++) {
                const int ksc = wid * 4 + ksl;
                const int ksg = ch * 32 + ksc;
                uint4 A0 = *(const uint4*)&Wf[(0 * 128 + ksg) * 128 + lane * 4];
                uint4 A1 = *(const uint4*)&Wf[(1 * 128 + ksg) * 128 + lane * 4];
#pragma unroll
                for (int ng = 0; ng < 4; ng++) {
                    const int tsrc = ksc * 8 + ng * 2 + (lane >> 4);
                    uint2 Bv = *(const uint2*)((const uint32_t*)Bw + tsrc * 36 + (lane & 15) * 2);
                    mma_tf32(acc[0][ng][0], acc[0][ng][1], acc[0][ng][2], acc[0][ng][3],
                             A0.x, A0.y, A0.z, A0.w, Bv.x, Bv.y);
                    mma_tf32(acc[1][ng][0], acc[1][ng][1], acc[1][ng][2], acc[1][ng][3],
                             A1.x, A1.y, A1.z, A1.w, Bv.x, Bv.y);
                }
            }
            __syncthreads();
        }

#pragma unroll
        for (int mt = 0; mt < 2; mt++) {
#pragma unroll
            for (int ng = 0; ng < 4; ng++) {
                int c0 = mt * 16 + (lane >> 2);
                int b0 = ng * 8 + 2 * (lane & 3);
                *(float2*)&red[(wid * 32 + c0) * RSTRIDE + b0] =
                    make_float2(acc[mt][ng][0], acc[mt][ng][1]);
                *(float2*)&red[(wid * 32 + c0 + 8) * RSTRIDE + b0] =
                    make_float2(acc[mt][ng][2], acc[mt][ng][3]);
            }
        }
        __syncthreads();

        {
            float gate[4];
#pragma unroll
            for (int g = 0; g < 4; g++) {
                float s = xp[g];
#pragma unroll
                for (int w = 0; w < 8; w++)
                    s += red[(w * 32 + g * 8 + hh_e) * RSTRIDE + b_e];
                gate[g] = s;
            }
            float iv = 1.f / (1.f + __expf(-gate[0]));
            float fv = 1.f / (1.f + __expf(-gate[1]));
            float gv = tanhf(gate[2]);
            float ov = 1.f / (1.f + __expf(-gate[3]));
            cstate = fv * cstate + iv * gv;
            float hv = ov * tanhf(cstate);
            g_hT[(t + 1) & 1][(hb + hh_e) * BB + b_e] = __uint_as_float(f2tf32(hv));
            g_hs[((size_t)b_e * SS + t) * HH + hb + hh_e] = hv;
        }

        grid_barrier();
    }
}

// ---------------------------------------------------------------------------
// Launch
// ---------------------------------------------------------------------------
extern "C" void kernel_launch(void* const* d_in, const int* in_sizes, int n_in,
                              void* d_out, int out_size) {
    const float* x     = (const float*)d_in[0];
    const float* W_ih  = (const float*)d_in[1];
    const float* W_hh  = (const float*)d_in[2];
    const float* b_ih  = (const float*)d_in[3];
    const float* b_hh  = (const float*)d_in[4];
    const float* W_key = (const float*)d_in[5];
    const float* b_key = (const float*)d_in[6];
    const float* W_val = (const float*)d_in[7];
    const float* b_val = (const float*)d_in[8];
    float* out = (float*)d_out;

    float* xg_ptr = nullptr;
    float* hs_ptr = nullptr;
    cudaGetSymbolAddress((void**)&xg_ptr, g_xg);
    cudaGetSymbolAddress((void**)&hs_ptr, g_hs);

    const int M = BB * SS;   // 32768
    const int LSTM_SMEM = (32768 + 2 * 9216) * 4;   // 204,800 B
    const int GEMM_SMEM = 16384 * 4;                // 65,536 B

    cudaFuncSetAttribute(lstm_persistent,
                         cudaFuncAttributeMaxDynamicSharedMemorySize, LSTM_SMEM);
    cudaFuncSetAttribute(gemm_tf32,
                         cudaFuncAttributeMaxDynamicSharedMemorySize, GEMM_SMEM);

    // Phase A: xg = x @ W_ih^T + b_ih + b_hh   [32768 x 4096], K=512
    {
        dim3 grid(GG / 128, M / 128);
        gemm_tf32<<<grid, 256, GEMM_SMEM>>>(x, W_ih, b_ih, b_hh, xg_ptr, M, GG, EE);
    }

    // Phase B: persistent tf32-MMA LSTM recurrence (single launch)
    lstm_persistent<<<NBLK, NTHR, LSTM_SMEM>>>(W_hh);

    // Phase C: keys / values projections [32768 x 512], K=1024
    {
        dim3 grid(DKV / 128, M / 128);
        gemm_tf32<<<grid, 256, GEMM_SMEM>>>(hs_ptr, W_key, b_key, nullptr, out, M, DKV, HH);
        gemm_tf32<<<grid, 256, GEMM_SMEM>>>(hs_ptr, W_val, b_val, nullptr,
                                            out + (size_t)M * DKV, M, DKV, HH);
    }
}